// round 13
// baseline (speedup 1.0000x reference)
#include <cuda_runtime.h>
#include <cuda_fp16.h>
#include <math.h>
#include <stdint.h>

#define BATCH 2
#define SEQ   2048
#define NH    16
#define HD    64
#define DM    1024
#define MROWS (BATCH*SEQ)   /* 4096 */

/* ------------------------------------------------------------------ */
/* scratch                                                             */
/* ------------------------------------------------------------------ */
__device__ __half g_xh [(size_t)MROWS * DM];
__device__ __half g_wqh[(size_t)DM * DM];
__device__ __half g_wkh[(size_t)DM * DM];
__device__ __half g_wvh[(size_t)DM * DM];
__device__ __half g_woh[(size_t)DM * DM];
__device__ __half g_qh [(size_t)BATCH * NH * SEQ * HD]; /* [b,h,s,d], *0.125*log2e */
__device__ __half g_kh [(size_t)BATCH * NH * SEQ * HD]; /* [b,h,s,d] */
__device__ __half g_vth[(size_t)BATCH * NH * HD * SEQ]; /* [b,h,d,s] */
__device__ __half g_ath[(size_t)MROWS * DM];            /* [b,s,h*d] */
__device__ float  g_rope[SEQ * 32 * 2];

/* ------------------------------------------------------------------ */
/* helpers                                                             */
/* ------------------------------------------------------------------ */
__device__ __forceinline__ uint32_t smem_u32(const void* p)
{
    uint32_t a;
    asm("{ .reg .u64 t; cvta.to.shared.u64 t, %1; cvt.u32.u64 %0, t; }"
        : "=r"(a) : "l"(p));
    return a;
}

__device__ __forceinline__ void cpa16(uint32_t dst, const void* src)
{
    asm volatile("cp.async.cg.shared.global [%0], [%1], 16;" :: "r"(dst), "l"(src));
}
#define CP_COMMIT() asm volatile("cp.async.commit_group;" ::: "memory")
#define CP_WAIT0()  asm volatile("cp.async.wait_group 0;" ::: "memory")
#define CP_WAIT1()  asm volatile("cp.async.wait_group 1;" ::: "memory")

__device__ __forceinline__ void mma16(float* c, uint32_t a0, uint32_t a1,
                                      uint32_t a2, uint32_t a3,
                                      uint32_t b0, uint32_t b1)
{
    asm("mma.sync.aligned.m16n8k16.row.col.f32.f16.f16.f32 "
        "{%0,%1,%2,%3},{%4,%5,%6,%7},{%8,%9},{%0,%1,%2,%3};"
        : "+f"(c[0]), "+f"(c[1]), "+f"(c[2]), "+f"(c[3])
        : "r"(a0), "r"(a1), "r"(a2), "r"(a3), "r"(b0), "r"(b1));
}

__device__ __forceinline__ void ldm4(uint32_t* r, uint32_t addr)
{
    asm volatile("ldmatrix.sync.aligned.m8n8.x4.shared.b16 {%0,%1,%2,%3}, [%4];"
        : "=r"(r[0]), "=r"(r[1]), "=r"(r[2]), "=r"(r[3]) : "r"(addr));
}

__device__ __forceinline__ uint32_t h2pack(float a, float b)
{
    __half2 h = __floats2half2_rn(a, b);
    return *(uint32_t*)&h;
}

/* ------------------------------------------------------------------ */
/* prepass                                                             */
/* ------------------------------------------------------------------ */
__global__ void f2h_k(const float* __restrict__ src, __half* __restrict__ dst, int n4)
{
    int i = blockIdx.x * blockDim.x + threadIdx.x;
    if (i >= n4) return;
    float4 v = ((const float4*)src)[i];
    ((uint2*)dst)[i] = make_uint2(h2pack(v.x, v.y), h2pack(v.z, v.w));
}

__global__ void f2h4_k(const float* s0, const float* s1, const float* s2,
                       const float* s3, __half* d0, __half* d1, __half* d2,
                       __half* d3, int n4)
{
    int i = blockIdx.x * blockDim.x + threadIdx.x;
    if (i >= n4) return;
    const float* s; __half* d;
    switch (blockIdx.y) {
        case 0: s = s0; d = d0; break;
        case 1: s = s1; d = d1; break;
        case 2: s = s2; d = d2; break;
        default: s = s3; d = d3; break;
    }
    float4 v = ((const float4*)s)[i];
    ((uint2*)d)[i] = make_uint2(h2pack(v.x, v.y), h2pack(v.z, v.w));
}

__global__ void rope_fill(const int* __restrict__ pos)
{
    int idx = blockIdx.x * blockDim.x + threadIdx.x;
    if (idx >= SEQ * 32) return;
    int s = idx >> 5, p = idx & 31;
    float ff  = (float)(1.0 / pow(10000.0, (double)(2 * p) / 64.0));
    float ang = (float)pos[s] * ff;
    double a  = (double)ang;
    g_rope[idx * 2 + 0] = (float)cos(a);
    g_rope[idx * 2 + 1] = (float)sin(a);
}

/* ------------------------------------------------------------------ */
/* fp16 GEMM: CTA 128x256, warp tile 64x64 (2x4 warps), BK=64,         */
/* 3-stage cp.async. modes as before.                                  */
/* ------------------------------------------------------------------ */
#define GBK   64
#define KSH   72                       /* half stride: 144B, cf for ldmatrix */
#define ABUFH (128 * KSH)              /* A: 128 rows  */
#define BBUFH (256 * KSH)              /* B: 256 rows  */
#define STGH  (ABUFH + BBUFH)          /* 27648 halfs = 55296 B */
#define NSTG  3
#define NCH   (DM / GBK)               /* 16 */
#define GSMEM (NSTG * STGH * 2)        /* 165888 B */

__device__ __forceinline__ void gemm_body(const __half* __restrict__ A,
                                          const __half* __restrict__ Bw,
                                          void* __restrict__ Cp, int mode,
                                          __half* hsm, int m0, int n0)
{
    uint32_t sbase = smem_u32(hsm);
    int t = threadIdx.x, lane = t & 31, w = t >> 5;
    int g = lane >> 2, tq = lane & 3;
    int wm = (w & 1) * 64, wn = (w >> 1) * 64;

    float acc[4][8][4];
#pragma unroll
    for (int mf = 0; mf < 4; mf++)
#pragma unroll
        for (int nf = 0; nf < 8; nf++)
#pragma unroll
            for (int i = 0; i < 4; i++) acc[mf][nf][i] = 0.0f;

    int arow = (lane & 7) + ((lane >> 3) & 1) * 8;
    int akoff = (lane >> 4) * 8;
    int brow = (lane & 7) + ((lane >> 4) & 1) * 8;
    int bkoff = ((lane >> 3) & 1) * 8;
    uint32_t a_off[4], b_off[4];
#pragma unroll
    for (int mf = 0; mf < 4; mf++)
        a_off[mf] = ((wm + mf * 16 + arow) * KSH + akoff) * 2;
#pragma unroll
    for (int p = 0; p < 4; p++)
        b_off[p] = ((wn + p * 16 + brow) * KSH + bkoff) * 2 + ABUFH * 2;

#define G_LOAD(cn, st) do {                                                   \
        uint32_t sa = sbase + (uint32_t)(st) * (STGH * 2);                    \
        uint32_t sbb = sa + ABUFH * 2;                                        \
        _Pragma("unroll")                                                     \
        for (int i = 0; i < 4; i++) {                                         \
            int idx = i * 256 + t, row = idx >> 3, c8 = idx & 7;              \
            cpa16(sa  + row * (KSH * 2) + c8 * 16,                            \
                  A  + (size_t)(m0 + row) * DM + (cn) * GBK + c8 * 8);        \
        }                                                                     \
        _Pragma("unroll")                                                     \
        for (int i = 0; i < 8; i++) {                                         \
            int idx = i * 256 + t, row = idx >> 3, c8 = idx & 7;              \
            cpa16(sbb + row * (KSH * 2) + c8 * 16,                            \
                  Bw + (size_t)(n0 + row) * DM + (cn) * GBK + c8 * 8);        \
        }                                                                     \
        CP_COMMIT();                                                          \
    } while (0)

    G_LOAD(0, 0);
    G_LOAD(1, 1);

#pragma unroll 1
    for (int c = 0; c < NCH; c++) {
        CP_WAIT1();
        __syncthreads();
        if (c + 2 < NCH) G_LOAD(c + 2, (c + 2) % NSTG);

        uint32_t stb = sbase + (uint32_t)(c % NSTG) * (STGH * 2);
#pragma unroll
        for (int ks = 0; ks < 4; ks++) {
            uint32_t kb = ks * 32;
            uint32_t af[4][4], bf[4][4];
#pragma unroll
            for (int mf = 0; mf < 4; mf++) ldm4(af[mf], stb + a_off[mf] + kb);
#pragma unroll
            for (int p = 0; p < 4; p++)    ldm4(bf[p], stb + b_off[p] + kb);
#pragma unroll
            for (int mf = 0; mf < 4; mf++)
#pragma unroll
                for (int nf = 0; nf < 8; nf++)
                    mma16(acc[mf][nf], af[mf][0], af[mf][1], af[mf][2], af[mf][3],
                          bf[nf >> 1][(nf & 1) * 2], bf[nf >> 1][(nf & 1) * 2 + 1]);
        }
    }
#undef G_LOAD
    __syncthreads();

    if (mode == 3) {
        /* V: fp16 transposed [b,h,d,s]; 4 blocks of 32x32 per warp */
        float* stg = (float*)hsm + w * (32 * 33);
        int bb = m0 >> 11;
#pragma unroll
        for (int hf = 0; hf < 2; hf++) {
#pragma unroll
            for (int vf = 0; vf < 2; vf++) {
#pragma unroll
                for (int mfl = 0; mfl < 2; mfl++) {
                    int mf = hf * 2 + mfl;
                    int rl = mfl * 16 + g;
#pragma unroll
                    for (int nfl = 0; nfl < 4; nfl++) {
                        int nf = vf * 4 + nfl;
                        int cl = nfl * 8 + 2 * tq;
                        stg[rl * 33 + cl]           = acc[mf][nf][0];
                        stg[rl * 33 + cl + 1]       = acc[mf][nf][1];
                        stg[(rl + 8) * 33 + cl]     = acc[mf][nf][2];
                        stg[(rl + 8) * 33 + cl + 1] = acc[mf][nf][3];
                    }
                }
                __syncwarp();
                int gn = n0 + wn + vf * 32 + lane;
                int hh = gn >> 6, dd = gn & 63;
                int s0 = (m0 + wm + hf * 32) & (SEQ - 1);
                uint32_t u[16];
#pragma unroll
                for (int i = 0; i < 16; i++)
                    u[i] = h2pack(stg[(2 * i) * 33 + lane],
                                  stg[(2 * i + 1) * 33 + lane]);
                uint4* dv = (uint4*)((__half*)Cp +
                            ((size_t)(bb * NH + hh) * HD + dd) * SEQ + s0);
                dv[0] = make_uint4(u[0],  u[1],  u[2],  u[3]);
                dv[1] = make_uint4(u[4],  u[5],  u[6],  u[7]);
                dv[2] = make_uint4(u[8],  u[9],  u[10], u[11]);
                dv[3] = make_uint4(u[12], u[13], u[14], u[15]);
                __syncwarp();
            }
        }
        return;
    }

    float qscale = (mode == 1) ? 0.125f * 1.4426950408889634f : 1.0f;
#pragma unroll
    for (int mf = 0; mf < 4; mf++)
#pragma unroll
        for (int i2 = 0; i2 < 2; i2++) {
            int gm = m0 + wm + mf * 16 + g + i2 * 8;
#pragma unroll
            for (int nf = 0; nf < 8; nf++) {
                int gn = n0 + wn + nf * 8 + 2 * tq;
                float v0 = acc[mf][nf][i2 * 2 + 0];
                float v1 = acc[mf][nf][i2 * 2 + 1];
                if (mode == 0) {
                    *(float2*)((float*)Cp + (size_t)gm * DM + gn) = make_float2(v0, v1);
                } else {
                    int bb = gm >> 11, ss = gm & (SEQ - 1);
                    int hh = gn >> 6,  dd = gn & 63;
                    int p = dd >> 1;
                    float cv = g_rope[(ss * 32 + p) * 2 + 0];
                    float sv = g_rope[(ss * 32 + p) * 2 + 1];
                    uint32_t h = h2pack((v0 * cv - v1 * sv) * qscale,
                                        (v0 * sv + v1 * cv) * qscale);
                    *(uint32_t*)((__half*)Cp +
                        (((size_t)(bb * NH + hh) * SEQ) + ss) * HD + dd) = h;
                }
            }
        }
}

__global__ __launch_bounds__(256, 1) void gemm_qkv(const __half* __restrict__ xh,
    const __half* __restrict__ wq, const __half* __restrict__ wk,
    const __half* __restrict__ wv, __half* __restrict__ qh,
    __half* __restrict__ kh, __half* __restrict__ vth)
{
    extern __shared__ __half hsm[];
    const __half* Bw; void* Cp; int mode;
    if (blockIdx.z == 0)      { Bw = wq; Cp = qh;  mode = 1; }
    else if (blockIdx.z == 1) { Bw = wk; Cp = kh;  mode = 2; }
    else                      { Bw = wv; Cp = vth; mode = 3; }
    gemm_body(xh, Bw, Cp, mode, hsm, blockIdx.y * 128, blockIdx.x * 256);
}

__global__ __launch_bounds__(256, 1) void gemm_out(const __half* __restrict__ A,
    const __half* __restrict__ Bw, float* __restrict__ C)
{
    extern __shared__ __half hsm[];
    gemm_body(A, Bw, C, 0, hsm, blockIdx.y * 128, blockIdx.x * 256);
}

/* ------------------------------------------------------------------ */
/* fp16 flash, base-2 softmax. unchanged from R12.                     */
/* ------------------------------------------------------------------ */
#define FQS 72
#define FVS 136
#define FOFF_K (128 * FQS)
#define FOFF_V (FOFF_K + 2 * 128 * FQS)
#define FSMEM  ((FOFF_V + 2 * 64 * FVS) * 2)   /* 90112 B */

__global__ __launch_bounds__(256) void flash_h(const __half* __restrict__ gq,
                                               const __half* __restrict__ gk,
                                               const __half* __restrict__ gv,
                                               __half* __restrict__ gout)
{
    extern __shared__ __half fsm[];
    uint32_t sbase = smem_u32(fsm);

    int t = threadIdx.x, lane = t & 31, w = t >> 5;
    int g = lane >> 2, tq = lane & 3;
    int qt = gridDim.x - 1 - blockIdx.x;
    int bh = blockIdx.y;
    int qr = w * 16 + g;

    const __half* Qg = gq + ((size_t)bh * SEQ + qt * 128) * HD;
    const __half* Kg = gk + (size_t)bh * SEQ * HD;
    const __half* Vg = gv + (size_t)bh * HD * SEQ;

#define F_LOADKV(ktp, nb) do {                                                \
        const __half* Kn = Kg + (size_t)(ktp) * 128 * HD;                     \
        _Pragma("unroll")                                                     \
        for (int i = 0; i < 4; i++) {                                         \
            int idx = i * 256 + t, row = idx >> 3, c8 = idx & 7;              \
            cpa16(sbase + (FOFF_K + ((nb) * 128 + row) * FQS) * 2 + c8 * 16,  \
                  Kn + row * HD + c8 * 8);                                    \
        }                                                                     \
        _Pragma("unroll")                                                     \
        for (int i = 0; i < 4; i++) {                                         \
            int idx = i * 256 + t, row = idx >> 4, c16 = idx & 15;            \
            cpa16(sbase + (FOFF_V + ((nb) * 64 + row) * FVS) * 2 + c16 * 16,  \
                  Vg + (size_t)row * SEQ + (ktp) * 128 + c16 * 8);            \
        }                                                                     \
        CP_COMMIT();                                                          \
    } while (0)

#pragma unroll
    for (int i = 0; i < 4; i++) {
        int idx = i * 256 + t, row = idx >> 3, c8 = idx & 7;
        cpa16(sbase + row * (FQS * 2) + c8 * 16, Qg + row * HD + c8 * 8);
    }
    F_LOADKV(0, 0);

    int arow = (lane & 7) + ((lane >> 3) & 1) * 8;
    int akoff = (lane >> 4) * 8;
    int brow = (lane & 7) + ((lane >> 4) & 1) * 8;
    int bkoff = ((lane >> 3) & 1) * 8;
    uint32_t q_off = ((w * 16 + arow) * FQS + akoff) * 2;
    uint32_t k_off[4], v_off[4];
#pragma unroll
    for (int p = 0; p < 4; p++) {
        k_off[p] = ((p * 16 + brow) * FQS + bkoff) * 2;
        v_off[p] = ((p * 16 + brow) * FVS + bkoff) * 2;
    }

    uint32_t qa[4][4];
    float o[8][4];
#pragma unroll
    for (int nf = 0; nf < 8; nf++)
#pragma unroll
        for (int i = 0; i < 4; i++) o[nf][i] = 0.0f;
    float m0r = -1e30f, m1r = -1e30f, l0 = 0.0f, l1 = 0.0f;
    const unsigned FULL = 0xffffffffu;

    int nktp = qt + 1;
#pragma unroll 1
    for (int ktp = 0; ktp < nktp; ktp++) {
        CP_WAIT0();
        __syncthreads();
        if (ktp + 1 < nktp) F_LOADKV(ktp + 1, (ktp + 1) & 1);

        if (ktp == 0) {
#pragma unroll
            for (int ks = 0; ks < 4; ks++) ldm4(qa[ks], sbase + q_off + ks * 32);
        }

        uint32_t kbb = sbase + (FOFF_K + (ktp & 1) * 128 * FQS) * 2;
        uint32_t vbb = sbase + (FOFF_V + (ktp & 1) * 64 * FVS) * 2;

#pragma unroll
        for (int hlf = 0; hlf < 2; hlf++) {
            int kt64 = ktp * 2 + hlf;
            if (kt64 * 64 > qt * 128 + w * 16 + 15) continue;

            uint32_t kbase = kbb + hlf * (64 * FQS * 2);
            uint32_t vkoff = hlf * 128;

            float s[8][4];
#pragma unroll
            for (int nf = 0; nf < 8; nf++)
                s[nf][0] = s[nf][1] = s[nf][2] = s[nf][3] = 0.0f;
#pragma unroll
            for (int ks = 0; ks < 4; ks++) {
                uint32_t kr[4][4];
#pragma unroll
                for (int p = 0; p < 4; p++) ldm4(kr[p], kbase + k_off[p] + ks * 32);
#pragma unroll
                for (int nf = 0; nf < 8; nf++)
                    mma16(s[nf], qa[ks][0], qa[ks][1], qa[ks][2], qa[ks][3],
                          kr[nf >> 1][(nf & 1) * 2], kr[nf >> 1][(nf & 1) * 2 + 1]);
            }

            int gi0 = qt * 128 + w * 16 + g;
            if (kt64 * 64 + 63 > gi0) {
#pragma unroll
                for (int nf = 0; nf < 8; nf++)
#pragma unroll
                    for (int j = 0; j < 4; j++) {
                        int col = kt64 * 64 + nf * 8 + 2 * tq + (j & 1);
                        int row = gi0 + (j >> 1) * 8;
                        if (col > row) s[nf][j] = -1e30f;
                    }
            }

            float mt0 = -1e30f, mt1 = -1e30f;
#pragma unroll
            for (int nf = 0; nf < 8; nf++) {
                mt0 = fmaxf(mt0, fmaxf(s[nf][0], s[nf][1]));
                mt1 = fmaxf(mt1, fmaxf(s[nf][2], s[nf][3]));
            }
            mt0 = fmaxf(mt0, __shfl_xor_sync(FULL, mt0, 1));
            mt0 = fmaxf(mt0, __shfl_xor_sync(FULL, mt0, 2));
            mt1 = fmaxf(mt1, __shfl_xor_sync(FULL, mt1, 1));
            mt1 = fmaxf(mt1, __shfl_xor_sync(FULL, mt1, 2));
            float mn0 = fmaxf(m0r, mt0), mn1 = fmaxf(m1r, mt1);
            float al0 = exp2f(m0r - mn0), al1 = exp2f(m1r - mn1);
            float ps0 = 0.0f, ps1 = 0.0f;
#pragma unroll
            for (int nf = 0; nf < 8; nf++) {
                s[nf][0] = exp2f(s[nf][0] - mn0);
                s[nf][1] = exp2f(s[nf][1] - mn0);
                s[nf][2] = exp2f(s[nf][2] - mn1);
                s[nf][3] = exp2f(s[nf][3] - mn1);
                ps0 += s[nf][0] + s[nf][1];
                ps1 += s[nf][2] + s[nf][3];
            }
            ps0 += __shfl_xor_sync(FULL, ps0, 1);
            ps0 += __shfl_xor_sync(FULL, ps0, 2);
            ps1 += __shfl_xor_sync(FULL, ps1, 1);
            ps1 += __shfl_xor_sync(FULL, ps1, 2);
            l0 = l0 * al0 + ps0;  l1 = l1 * al1 + ps1;
            m0r = mn0;  m1r = mn1;
#pragma unroll
            for (int nf = 0; nf < 8; nf++) {
                o[nf][0] *= al0; o[nf][1] *= al0;
                o[nf][2] *= al1; o[nf][3] *= al1;
            }

#pragma unroll
            for (int ks = 0; ks < 4; ks++) {
                uint32_t pa0 = h2pack(s[2 * ks][0],     s[2 * ks][1]);
                uint32_t pa1 = h2pack(s[2 * ks][2],     s[2 * ks][3]);
                uint32_t pa2 = h2pack(s[2 * ks + 1][0], s[2 * ks + 1][1]);
                uint32_t pa3 = h2pack(s[2 * ks + 1][2], s[2 * ks + 1][3]);
                uint32_t vr[4][4];
#pragma unroll
                for (int p = 0; p < 4; p++)
                    ldm4(vr[p], vbb + v_off[p] + vkoff + ks * 32);
#pragma unroll
                for (int nf = 0; nf < 8; nf++)
                    mma16(o[nf], pa0, pa1, pa2, pa3,
                          vr[nf >> 1][(nf & 1) * 2], vr[nf >> 1][(nf & 1) * 2 + 1]);
            }
        }
    }
#undef F_LOADKV

    int b = bh >> 4, h = bh & 15;
    float inv0 = 1.0f / l0, inv1 = 1.0f / l1;
    int s0 = qt * 128 + qr;
#pragma unroll
    for (int nf = 0; nf < 8; nf++) {
        int d = nf * 8 + 2 * tq;
        *(uint32_t*)(gout + ((size_t)b * SEQ + s0) * DM + h * 64 + d) =
            h2pack(o[nf][0] * inv0, o[nf][1] * inv0);
        *(uint32_t*)(gout + ((size_t)b * SEQ + s0 + 8) * DM + h * 64 + d) =
            h2pack(o[nf][2] * inv1, o[nf][3] * inv1);
    }
}

/* ------------------------------------------------------------------ */
extern "C" void kernel_launch(void* const* d_in, const int* in_sizes, int n_in,
                              void* d_out, int out_size)
{
    const float* x  = (const float*)d_in[0];
    const float* Wq = (const float*)d_in[1];
    const float* Wk = (const float*)d_in[2];
    const float* Wv = (const float*)d_in[3];
    const float* Wo = (const float*)d_in[4];
    const int*  pos = (const int*)d_in[6];
    float* out = (float*)d_out;

    __half *xh, *wqh, *wkh, *wvh, *woh, *qh, *kh, *vth, *ath;
    cudaGetSymbolAddress((void**)&xh,  g_xh);
    cudaGetSymbolAddress((void**)&wqh, g_wqh);
    cudaGetSymbolAddress((void**)&wkh, g_wkh);
    cudaGetSymbolAddress((void**)&wvh, g_wvh);
    cudaGetSymbolAddress((void**)&woh, g_woh);
    cudaGetSymbolAddress((void**)&qh,  g_qh);
    cudaGetSymbolAddress((void**)&kh,  g_kh);
    cudaGetSymbolAddress((void**)&vth, g_vth);
    cudaGetSymbolAddress((void**)&ath, g_ath);

    cudaFuncSetAttribute(gemm_qkv, cudaFuncAttributeMaxDynamicSharedMemorySize, GSMEM);
    cudaFuncSetAttribute(gemm_out, cudaFuncAttributeMaxDynamicSharedMemorySize, GSMEM);
    cudaFuncSetAttribute(flash_h,  cudaFuncAttributeMaxDynamicSharedMemorySize, FSMEM);

    int nx4 = MROWS * DM / 4, nw4 = DM * DM / 4;
    f2h_k<<<(nx4 + 255) / 256, 256>>>(x, xh, nx4);
    f2h4_k<<<dim3((nw4 + 255) / 256, 4), 256>>>(Wq, Wk, Wv, Wo,
                                                wqh, wkh, wvh, woh, nw4);
    rope_fill<<<256, 256>>>(pos);

    gemm_qkv<<<dim3(DM / 256, MROWS / 128, 3), 256, GSMEM>>>(
        xh, wqh, wkh, wvh, qh, kh, vth);

    flash_h<<<dim3(SEQ / 128, BATCH * NH), 256, FSMEM>>>(qh, kh, vth, ath);

    gemm_out<<<dim3(DM / 256, MROWS / 128), 256, GSMEM>>>(ath, woh, out);
}

// round 14
// speedup vs baseline: 1.0711x; 1.0711x over previous
#include <cuda_runtime.h>
#include <cuda_fp16.h>
#include <math.h>
#include <stdint.h>

#define BATCH 2
#define SEQ   2048
#define NH    16
#define HD    64
#define DM    1024
#define MROWS (BATCH*SEQ)   /* 4096 */

/* ------------------------------------------------------------------ */
/* scratch                                                             */
/* ------------------------------------------------------------------ */
__device__ __half g_xh [(size_t)MROWS * DM];
__device__ __half g_wqh[(size_t)DM * DM];
__device__ __half g_wkh[(size_t)DM * DM];
__device__ __half g_wvh[(size_t)DM * DM];
__device__ __half g_woh[(size_t)DM * DM];
__device__ __half g_qh [(size_t)BATCH * NH * SEQ * HD]; /* [b,h,s,d], *0.125*log2e */
__device__ __half g_kh [(size_t)BATCH * NH * SEQ * HD]; /* [b,h,s,d] */
__device__ __half g_vth[(size_t)BATCH * NH * HD * SEQ]; /* [b,h,d,s] */
__device__ __half g_ath[(size_t)MROWS * DM];            /* [b,s,h*d] */
__device__ float  g_rope[SEQ * 32 * 2];

/* ------------------------------------------------------------------ */
/* helpers                                                             */
/* ------------------------------------------------------------------ */
__device__ __forceinline__ uint32_t smem_u32(const void* p)
{
    uint32_t a;
    asm("{ .reg .u64 t; cvta.to.shared.u64 t, %1; cvt.u32.u64 %0, t; }"
        : "=r"(a) : "l"(p));
    return a;
}

__device__ __forceinline__ void cpa16(uint32_t dst, const void* src)
{
    asm volatile("cp.async.cg.shared.global [%0], [%1], 16;" :: "r"(dst), "l"(src));
}
#define CP_COMMIT() asm volatile("cp.async.commit_group;" ::: "memory")
#define CP_WAIT0()  asm volatile("cp.async.wait_group 0;" ::: "memory")
#define CP_WAIT1()  asm volatile("cp.async.wait_group 1;" ::: "memory")

__device__ __forceinline__ void mma16(float* c, uint32_t a0, uint32_t a1,
                                      uint32_t a2, uint32_t a3,
                                      uint32_t b0, uint32_t b1)
{
    asm("mma.sync.aligned.m16n8k16.row.col.f32.f16.f16.f32 "
        "{%0,%1,%2,%3},{%4,%5,%6,%7},{%8,%9},{%0,%1,%2,%3};"
        : "+f"(c[0]), "+f"(c[1]), "+f"(c[2]), "+f"(c[3])
        : "r"(a0), "r"(a1), "r"(a2), "r"(a3), "r"(b0), "r"(b1));
}

__device__ __forceinline__ void ldm4(uint32_t* r, uint32_t addr)
{
    asm volatile("ldmatrix.sync.aligned.m8n8.x4.shared.b16 {%0,%1,%2,%3}, [%4];"
        : "=r"(r[0]), "=r"(r[1]), "=r"(r[2]), "=r"(r[3]) : "r"(addr));
}

__device__ __forceinline__ uint32_t h2pack(float a, float b)
{
    __half2 h = __floats2half2_rn(a, b);
    return *(uint32_t*)&h;
}

/* ------------------------------------------------------------------ */
/* prepass                                                             */
/* ------------------------------------------------------------------ */
__global__ void f2h_k(const float* __restrict__ src, __half* __restrict__ dst, int n4)
{
    int i = blockIdx.x * blockDim.x + threadIdx.x;
    if (i >= n4) return;
    float4 v = ((const float4*)src)[i];
    ((uint2*)dst)[i] = make_uint2(h2pack(v.x, v.y), h2pack(v.z, v.w));
}

__global__ void f2h4_k(const float* s0, const float* s1, const float* s2,
                       const float* s3, __half* d0, __half* d1, __half* d2,
                       __half* d3, int n4)
{
    int i = blockIdx.x * blockDim.x + threadIdx.x;
    if (i >= n4) return;
    const float* s; __half* d;
    switch (blockIdx.y) {
        case 0: s = s0; d = d0; break;
        case 1: s = s1; d = d1; break;
        case 2: s = s2; d = d2; break;
        default: s = s3; d = d3; break;
    }
    float4 v = ((const float4*)s)[i];
    ((uint2*)d)[i] = make_uint2(h2pack(v.x, v.y), h2pack(v.z, v.w));
}

__global__ void rope_fill(const int* __restrict__ pos)
{
    int idx = blockIdx.x * blockDim.x + threadIdx.x;
    if (idx >= SEQ * 32) return;
    int s = idx >> 5, p = idx & 31;
    float ff  = (float)(1.0 / pow(10000.0, (double)(2 * p) / 64.0));
    float ang = (float)pos[s] * ff;
    double a  = (double)ang;
    g_rope[idx * 2 + 0] = (float)cos(a);
    g_rope[idx * 2 + 1] = (float)sin(a);
}

/* ------------------------------------------------------------------ */
/* fp16 GEMM (R11 best config): 128x128 tile, warp 64x32, BK=64,       */
/* 2-stage cp.async. mode 0: fp32 row-major; 1: Q rope*0.125*log2e;    */
/* 2: K rope; 3: V [b,h,d,s]                                           */
/* ------------------------------------------------------------------ */
#define GBK   64
#define KSH   72
#define ABUFH (128 * KSH)
#define STGH  (2 * ABUFH)
#define NCH   (DM / GBK)             /* 16 */
#define GSMEM (2 * STGH * 2)         /* 73728 B */

__device__ __forceinline__ void gemm_body(const __half* __restrict__ A,
                                          const __half* __restrict__ Bw,
                                          void* __restrict__ Cp, int mode,
                                          __half* hsm, int m0, int n0)
{
    uint32_t sbase = smem_u32(hsm);
    int t = threadIdx.x, lane = t & 31, w = t >> 5;
    int g = lane >> 2, tq = lane & 3;
    int wm = (w & 1) * 64, wn = (w >> 1) * 32;

    float acc[4][4][4];
#pragma unroll
    for (int mf = 0; mf < 4; mf++)
#pragma unroll
        for (int nf = 0; nf < 4; nf++)
#pragma unroll
            for (int i = 0; i < 4; i++) acc[mf][nf][i] = 0.0f;

    int arow = (lane & 7) + ((lane >> 3) & 1) * 8;
    int akoff = (lane >> 4) * 8;
    int brow = (lane & 7) + ((lane >> 4) & 1) * 8;
    int bkoff = ((lane >> 3) & 1) * 8;
    uint32_t a_off[4], b_off[2];
#pragma unroll
    for (int mf = 0; mf < 4; mf++)
        a_off[mf] = ((wm + mf * 16 + arow) * KSH + akoff) * 2;
#pragma unroll
    for (int p = 0; p < 2; p++)
        b_off[p] = ((wn + p * 16 + brow) * KSH + bkoff) * 2 + ABUFH * 2;

#define G_LOAD(cn, st) do {                                                   \
        uint32_t sa = sbase + (uint32_t)(st) * (STGH * 2);                    \
        uint32_t sbb = sa + ABUFH * 2;                                        \
        _Pragma("unroll")                                                     \
        for (int i = 0; i < 4; i++) {                                         \
            int idx = i * 256 + t, row = idx >> 3, c8 = idx & 7;              \
            cpa16(sa  + row * (KSH * 2) + c8 * 16,                            \
                  A  + (size_t)(m0 + row) * DM + (cn) * GBK + c8 * 8);        \
            cpa16(sbb + row * (KSH * 2) + c8 * 16,                            \
                  Bw + (size_t)(n0 + row) * DM + (cn) * GBK + c8 * 8);        \
        }                                                                     \
        CP_COMMIT();                                                          \
    } while (0)

    G_LOAD(0, 0);
    G_LOAD(1, 1);

#pragma unroll 1
    for (int c = 0; c < NCH; c++) {
        if (c < NCH - 1) CP_WAIT1(); else CP_WAIT0();
        __syncthreads();

        uint32_t stb = sbase + (uint32_t)(c & 1) * (STGH * 2);
#pragma unroll
        for (int ks = 0; ks < 4; ks++) {
            uint32_t kb = ks * 32;
            uint32_t af[4][4], bf[2][4];
#pragma unroll
            for (int mf = 0; mf < 4; mf++) ldm4(af[mf], stb + a_off[mf] + kb);
#pragma unroll
            for (int p = 0; p < 2; p++)    ldm4(bf[p], stb + b_off[p] + kb);
#pragma unroll
            for (int mf = 0; mf < 4; mf++)
#pragma unroll
                for (int nf = 0; nf < 4; nf++)
                    mma16(acc[mf][nf], af[mf][0], af[mf][1], af[mf][2], af[mf][3],
                          bf[nf >> 1][(nf & 1) * 2], bf[nf >> 1][(nf & 1) * 2 + 1]);
        }
        __syncthreads();
        if (c + 2 < NCH) G_LOAD(c + 2, c & 1);
    }
#undef G_LOAD

    if (mode == 3) {
        float* stg = (float*)hsm + w * (32 * 33);
        int bb = m0 >> 11;
        int gn = n0 + wn + lane;
        int hh = gn >> 6, dd = gn & 63;
#pragma unroll
        for (int hf = 0; hf < 2; hf++) {
#pragma unroll
            for (int mfl = 0; mfl < 2; mfl++) {
                int mf = hf * 2 + mfl;
                int rl = mfl * 16 + g;
#pragma unroll
                for (int nf = 0; nf < 4; nf++) {
                    int cl = nf * 8 + 2 * tq;
                    stg[rl * 33 + cl]           = acc[mf][nf][0];
                    stg[rl * 33 + cl + 1]       = acc[mf][nf][1];
                    stg[(rl + 8) * 33 + cl]     = acc[mf][nf][2];
                    stg[(rl + 8) * 33 + cl + 1] = acc[mf][nf][3];
                }
            }
            __syncwarp();
            int s0 = (m0 + wm + hf * 32) & (SEQ - 1);
            uint32_t u[16];
#pragma unroll
            for (int i = 0; i < 16; i++)
                u[i] = h2pack(stg[(2 * i) * 33 + lane], stg[(2 * i + 1) * 33 + lane]);
            uint4* dv = (uint4*)((__half*)Cp +
                        ((size_t)(bb * NH + hh) * HD + dd) * SEQ + s0);
            dv[0] = make_uint4(u[0],  u[1],  u[2],  u[3]);
            dv[1] = make_uint4(u[4],  u[5],  u[6],  u[7]);
            dv[2] = make_uint4(u[8],  u[9],  u[10], u[11]);
            dv[3] = make_uint4(u[12], u[13], u[14], u[15]);
            __syncwarp();
        }
        return;
    }

    float qscale = (mode == 1) ? 0.125f * 1.4426950408889634f : 1.0f;
#pragma unroll
    for (int mf = 0; mf < 4; mf++)
#pragma unroll
        for (int i2 = 0; i2 < 2; i2++) {
            int gm = m0 + wm + mf * 16 + g + i2 * 8;
#pragma unroll
            for (int nf = 0; nf < 4; nf++) {
                int gn = n0 + wn + nf * 8 + 2 * tq;
                float v0 = acc[mf][nf][i2 * 2 + 0];
                float v1 = acc[mf][nf][i2 * 2 + 1];
                if (mode == 0) {
                    *(float2*)((float*)Cp + (size_t)gm * DM + gn) = make_float2(v0, v1);
                } else {
                    int bb = gm >> 11, ss = gm & (SEQ - 1);
                    int hh = gn >> 6,  dd = gn & 63;
                    int p = dd >> 1;
                    float cv = g_rope[(ss * 32 + p) * 2 + 0];
                    float sv = g_rope[(ss * 32 + p) * 2 + 1];
                    uint32_t h = h2pack((v0 * cv - v1 * sv) * qscale,
                                        (v0 * sv + v1 * cv) * qscale);
                    *(uint32_t*)((__half*)Cp +
                        (((size_t)(bb * NH + hh) * SEQ) + ss) * HD + dd) = h;
                }
            }
        }
}

__global__ __launch_bounds__(256, 2) void gemm_qkv(const __half* __restrict__ xh,
    const __half* __restrict__ wq, const __half* __restrict__ wk,
    const __half* __restrict__ wv, __half* __restrict__ qh,
    __half* __restrict__ kh, __half* __restrict__ vth)
{
    extern __shared__ __half hsm[];
    const __half* Bw; void* Cp; int mode;
    if (blockIdx.z == 0)      { Bw = wq; Cp = qh;  mode = 1; }
    else if (blockIdx.z == 1) { Bw = wk; Cp = kh;  mode = 2; }
    else                      { Bw = wv; Cp = vth; mode = 3; }
    gemm_body(xh, Bw, Cp, mode, hsm, blockIdx.y * 128, blockIdx.x * 128);
}

__global__ __launch_bounds__(256, 2) void gemm_out(const __half* __restrict__ A,
    const __half* __restrict__ Bw, float* __restrict__ C)
{
    extern __shared__ __half hsm[];
    gemm_body(A, Bw, C, 0, hsm, blockIdx.y * 128, blockIdx.x * 128);
}

/* ------------------------------------------------------------------ */
/* fp16 flash, base-2 softmax. Forced 2 CTAs/SM; Q fragments reloaded  */
/* from smem each iteration to fit the 128-reg budget.                 */
/* ------------------------------------------------------------------ */
#define FQS 72
#define FVS 136
#define FOFF_K (128 * FQS)
#define FOFF_V (FOFF_K + 2 * 128 * FQS)
#define FSMEM  ((FOFF_V + 2 * 64 * FVS) * 2)   /* 90112 B */

__global__ __launch_bounds__(256, 2) void flash_h(const __half* __restrict__ gq,
                                                  const __half* __restrict__ gk,
                                                  const __half* __restrict__ gv,
                                                  __half* __restrict__ gout)
{
    extern __shared__ __half fsm[];
    uint32_t sbase = smem_u32(fsm);

    int t = threadIdx.x, lane = t & 31, w = t >> 5;
    int g = lane >> 2, tq = lane & 3;
    int qt = gridDim.x - 1 - blockIdx.x;
    int bh = blockIdx.y;
    int qr = w * 16 + g;

    const __half* Qg = gq + ((size_t)bh * SEQ + qt * 128) * HD;
    const __half* Kg = gk + (size_t)bh * SEQ * HD;
    const __half* Vg = gv + (size_t)bh * HD * SEQ;

#define F_LOADKV(ktp, nb) do {                                                \
        const __half* Kn = Kg + (size_t)(ktp) * 128 * HD;                     \
        _Pragma("unroll")                                                     \
        for (int i = 0; i < 4; i++) {                                         \
            int idx = i * 256 + t, row = idx >> 3, c8 = idx & 7;              \
            cpa16(sbase + (FOFF_K + ((nb) * 128 + row) * FQS) * 2 + c8 * 16,  \
                  Kn + row * HD + c8 * 8);                                    \
        }                                                                     \
        _Pragma("unroll")                                                     \
        for (int i = 0; i < 4; i++) {                                         \
            int idx = i * 256 + t, row = idx >> 4, c16 = idx & 15;            \
            cpa16(sbase + (FOFF_V + ((nb) * 64 + row) * FVS) * 2 + c16 * 16,  \
                  Vg + (size_t)row * SEQ + (ktp) * 128 + c16 * 8);            \
        }                                                                     \
        CP_COMMIT();                                                          \
    } while (0)

#pragma unroll
    for (int i = 0; i < 4; i++) {
        int idx = i * 256 + t, row = idx >> 3, c8 = idx & 7;
        cpa16(sbase + row * (FQS * 2) + c8 * 16, Qg + row * HD + c8 * 8);
    }
    F_LOADKV(0, 0);

    int arow = (lane & 7) + ((lane >> 3) & 1) * 8;
    int akoff = (lane >> 4) * 8;
    int brow = (lane & 7) + ((lane >> 4) & 1) * 8;
    int bkoff = ((lane >> 3) & 1) * 8;
    uint32_t q_off = ((w * 16 + arow) * FQS + akoff) * 2;
    uint32_t k_off[4], v_off[4];
#pragma unroll
    for (int p = 0; p < 4; p++) {
        k_off[p] = ((p * 16 + brow) * FQS + bkoff) * 2;
        v_off[p] = ((p * 16 + brow) * FVS + bkoff) * 2;
    }

    float o[8][4];
#pragma unroll
    for (int nf = 0; nf < 8; nf++)
#pragma unroll
        for (int i = 0; i < 4; i++) o[nf][i] = 0.0f;
    float m0r = -1e30f, m1r = -1e30f, l0 = 0.0f, l1 = 0.0f;
    const unsigned FULL = 0xffffffffu;

    int nktp = qt + 1;
#pragma unroll 1
    for (int ktp = 0; ktp < nktp; ktp++) {
        CP_WAIT0();
        __syncthreads();
        if (ktp + 1 < nktp) F_LOADKV(ktp + 1, (ktp + 1) & 1);

        /* Q fragments reloaded per iteration (frees 16 regs) */
        uint32_t qa[4][4];
#pragma unroll
        for (int ks = 0; ks < 4; ks++) ldm4(qa[ks], sbase + q_off + ks * 32);

        uint32_t kbb = sbase + (FOFF_K + (ktp & 1) * 128 * FQS) * 2;
        uint32_t vbb = sbase + (FOFF_V + (ktp & 1) * 64 * FVS) * 2;

#pragma unroll
        for (int hlf = 0; hlf < 2; hlf++) {
            int kt64 = ktp * 2 + hlf;
            if (kt64 * 64 > qt * 128 + w * 16 + 15) continue;

            uint32_t kbase = kbb + hlf * (64 * FQS * 2);
            uint32_t vkoff = hlf * 128;

            float s[8][4];
#pragma unroll
            for (int nf = 0; nf < 8; nf++)
                s[nf][0] = s[nf][1] = s[nf][2] = s[nf][3] = 0.0f;
#pragma unroll
            for (int ks = 0; ks < 4; ks++) {
                uint32_t kr[4][4];
#pragma unroll
                for (int p = 0; p < 4; p++) ldm4(kr[p], kbase + k_off[p] + ks * 32);
#pragma unroll
                for (int nf = 0; nf < 8; nf++)
                    mma16(s[nf], qa[ks][0], qa[ks][1], qa[ks][2], qa[ks][3],
                          kr[nf >> 1][(nf & 1) * 2], kr[nf >> 1][(nf & 1) * 2 + 1]);
            }

            int gi0 = qt * 128 + w * 16 + g;
            if (kt64 * 64 + 63 > gi0) {
#pragma unroll
                for (int nf = 0; nf < 8; nf++)
#pragma unroll
                    for (int j = 0; j < 4; j++) {
                        int col = kt64 * 64 + nf * 8 + 2 * tq + (j & 1);
                        int row = gi0 + (j >> 1) * 8;
                        if (col > row) s[nf][j] = -1e30f;
                    }
            }

            float mt0 = -1e30f, mt1 = -1e30f;
#pragma unroll
            for (int nf = 0; nf < 8; nf++) {
                mt0 = fmaxf(mt0, fmaxf(s[nf][0], s[nf][1]));
                mt1 = fmaxf(mt1, fmaxf(s[nf][2], s[nf][3]));
            }
            mt0 = fmaxf(mt0, __shfl_xor_sync(FULL, mt0, 1));
            mt0 = fmaxf(mt0, __shfl_xor_sync(FULL, mt0, 2));
            mt1 = fmaxf(mt1, __shfl_xor_sync(FULL, mt1, 1));
            mt1 = fmaxf(mt1, __shfl_xor_sync(FULL, mt1, 2));
            float mn0 = fmaxf(m0r, mt0), mn1 = fmaxf(m1r, mt1);
            float al0 = exp2f(m0r - mn0), al1 = exp2f(m1r - mn1);
            float ps0 = 0.0f, ps1 = 0.0f;
#pragma unroll
            for (int nf = 0; nf < 8; nf++) {
                s[nf][0] = exp2f(s[nf][0] - mn0);
                s[nf][1] = exp2f(s[nf][1] - mn0);
                s[nf][2] = exp2f(s[nf][2] - mn1);
                s[nf][3] = exp2f(s[nf][3] - mn1);
                ps0 += s[nf][0] + s[nf][1];
                ps1 += s[nf][2] + s[nf][3];
            }
            ps0 += __shfl_xor_sync(FULL, ps0, 1);
            ps0 += __shfl_xor_sync(FULL, ps0, 2);
            ps1 += __shfl_xor_sync(FULL, ps1, 1);
            ps1 += __shfl_xor_sync(FULL, ps1, 2);
            l0 = l0 * al0 + ps0;  l1 = l1 * al1 + ps1;
            m0r = mn0;  m1r = mn1;
#pragma unroll
            for (int nf = 0; nf < 8; nf++) {
                o[nf][0] *= al0; o[nf][1] *= al0;
                o[nf][2] *= al1; o[nf][3] *= al1;
            }

#pragma unroll
            for (int ks = 0; ks < 4; ks++) {
                uint32_t pa0 = h2pack(s[2 * ks][0],     s[2 * ks][1]);
                uint32_t pa1 = h2pack(s[2 * ks][2],     s[2 * ks][3]);
                uint32_t pa2 = h2pack(s[2 * ks + 1][0], s[2 * ks + 1][1]);
                uint32_t pa3 = h2pack(s[2 * ks + 1][2], s[2 * ks + 1][3]);
                uint32_t vr[4][4];
#pragma unroll
                for (int p = 0; p < 4; p++)
                    ldm4(vr[p], vbb + v_off[p] + vkoff + ks * 32);
#pragma unroll
                for (int nf = 0; nf < 8; nf++)
                    mma16(o[nf], pa0, pa1, pa2, pa3,
                          vr[nf >> 1][(nf & 1) * 2], vr[nf >> 1][(nf & 1) * 2 + 1]);
            }
        }
    }
#undef F_LOADKV

    int b = bh >> 4, h = bh & 15;
    float inv0 = 1.0f / l0, inv1 = 1.0f / l1;
    int s0 = qt * 128 + qr;
#pragma unroll
    for (int nf = 0; nf < 8; nf++) {
        int d = nf * 8 + 2 * tq;
        *(uint32_t*)(gout + ((size_t)b * SEQ + s0) * DM + h * 64 + d) =
            h2pack(o[nf][0] * inv0, o[nf][1] * inv0);
        *(uint32_t*)(gout + ((size_t)b * SEQ + s0 + 8) * DM + h * 64 + d) =
            h2pack(o[nf][2] * inv1, o[nf][3] * inv1);
    }
}

/* ------------------------------------------------------------------ */
extern "C" void kernel_launch(void* const* d_in, const int* in_sizes, int n_in,
                              void* d_out, int out_size)
{
    const float* x  = (const float*)d_in[0];
    const float* Wq = (const float*)d_in[1];
    const float* Wk = (const float*)d_in[2];
    const float* Wv = (const float*)d_in[3];
    const float* Wo = (const float*)d_in[4];
    const int*  pos = (const int*)d_in[6];
    float* out = (float*)d_out;

    __half *xh, *wqh, *wkh, *wvh, *woh, *qh, *kh, *vth, *ath;
    cudaGetSymbolAddress((void**)&xh,  g_xh);
    cudaGetSymbolAddress((void**)&wqh, g_wqh);
    cudaGetSymbolAddress((void**)&wkh, g_wkh);
    cudaGetSymbolAddress((void**)&wvh, g_wvh);
    cudaGetSymbolAddress((void**)&woh, g_woh);
    cudaGetSymbolAddress((void**)&qh,  g_qh);
    cudaGetSymbolAddress((void**)&kh,  g_kh);
    cudaGetSymbolAddress((void**)&vth, g_vth);
    cudaGetSymbolAddress((void**)&ath, g_ath);

    cudaFuncSetAttribute(gemm_qkv, cudaFuncAttributeMaxDynamicSharedMemorySize, GSMEM);
    cudaFuncSetAttribute(gemm_out, cudaFuncAttributeMaxDynamicSharedMemorySize, GSMEM);
    cudaFuncSetAttribute(flash_h,  cudaFuncAttributeMaxDynamicSharedMemorySize, FSMEM);

    int nx4 = MROWS * DM / 4, nw4 = DM * DM / 4;
    f2h_k<<<(nx4 + 255) / 256, 256>>>(x, xh, nx4);
    f2h4_k<<<dim3((nw4 + 255) / 256, 4), 256>>>(Wq, Wk, Wv, Wo,
                                                wqh, wkh, wvh, woh, nw4);
    rope_fill<<<256, 256>>>(pos);

    gemm_qkv<<<dim3(DM / 128, MROWS / 128, 3), 256, GSMEM>>>(
        xh, wqh, wkh, wvh, qh, kh, vth);

    flash_h<<<dim3(SEQ / 128, BATCH * NH), 256, FSMEM>>>(qh, kh, vth, ath);

    gemm_out<<<dim3(DM / 128, MROWS / 128), 256, GSMEM>>>(ath, woh, out);
}

// round 15
// speedup vs baseline: 1.1469x; 1.0708x over previous
#include <cuda_runtime.h>
#include <cuda_fp16.h>
#include <math.h>
#include <stdint.h>

#define BATCH 2
#define SEQ   2048
#define NH    16
#define HD    64
#define DM    1024
#define MROWS (BATCH*SEQ)   /* 4096 */

/* ------------------------------------------------------------------ */
/* scratch                                                             */
/* ------------------------------------------------------------------ */
__device__ __half g_xh [(size_t)MROWS * DM];
__device__ __half g_wqh[(size_t)DM * DM];
__device__ __half g_wkh[(size_t)DM * DM];
__device__ __half g_wvh[(size_t)DM * DM];
__device__ __half g_woh[(size_t)DM * DM];
__device__ __half g_qh [(size_t)BATCH * NH * SEQ * HD]; /* [b,h,s,d], *0.125*log2e */
__device__ __half g_kh [(size_t)BATCH * NH * SEQ * HD]; /* [b,h,s,d] */
__device__ __half g_vth[(size_t)BATCH * NH * HD * SEQ]; /* [b,h,d,s] */
__device__ __half g_ath[(size_t)MROWS * DM];            /* [b,s,h*d] */
__device__ float  g_rope[SEQ * 32 * 2];
__device__ int    g_task;                                /* flash work queue */

#define NTASK (32 * 16)   /* (b*h) x q-tiles = 512 */

/* ------------------------------------------------------------------ */
/* helpers                                                             */
/* ------------------------------------------------------------------ */
__device__ __forceinline__ uint32_t smem_u32(const void* p)
{
    uint32_t a;
    asm("{ .reg .u64 t; cvta.to.shared.u64 t, %1; cvt.u32.u64 %0, t; }"
        : "=r"(a) : "l"(p));
    return a;
}

__device__ __forceinline__ void cpa16(uint32_t dst, const void* src)
{
    asm volatile("cp.async.cg.shared.global [%0], [%1], 16;" :: "r"(dst), "l"(src));
}
#define CP_COMMIT() asm volatile("cp.async.commit_group;" ::: "memory")
#define CP_WAIT0()  asm volatile("cp.async.wait_group 0;" ::: "memory")
#define CP_WAIT1()  asm volatile("cp.async.wait_group 1;" ::: "memory")

__device__ __forceinline__ void mma16(float* c, uint32_t a0, uint32_t a1,
                                      uint32_t a2, uint32_t a3,
                                      uint32_t b0, uint32_t b1)
{
    asm("mma.sync.aligned.m16n8k16.row.col.f32.f16.f16.f32 "
        "{%0,%1,%2,%3},{%4,%5,%6,%7},{%8,%9},{%0,%1,%2,%3};"
        : "+f"(c[0]), "+f"(c[1]), "+f"(c[2]), "+f"(c[3])
        : "r"(a0), "r"(a1), "r"(a2), "r"(a3), "r"(b0), "r"(b1));
}

__device__ __forceinline__ void ldm4(uint32_t* r, uint32_t addr)
{
    asm volatile("ldmatrix.sync.aligned.m8n8.x4.shared.b16 {%0,%1,%2,%3}, [%4];"
        : "=r"(r[0]), "=r"(r[1]), "=r"(r[2]), "=r"(r[3]) : "r"(addr));
}

__device__ __forceinline__ uint32_t h2pack(float a, float b)
{
    __half2 h = __floats2half2_rn(a, b);
    return *(uint32_t*)&h;
}

/* ------------------------------------------------------------------ */
/* prepass                                                             */
/* ------------------------------------------------------------------ */
__global__ void f2h_k(const float* __restrict__ src, __half* __restrict__ dst, int n4)
{
    int i = blockIdx.x * blockDim.x + threadIdx.x;
    if (i >= n4) return;
    float4 v = ((const float4*)src)[i];
    ((uint2*)dst)[i] = make_uint2(h2pack(v.x, v.y), h2pack(v.z, v.w));
}

__global__ void f2h4_k(const float* s0, const float* s1, const float* s2,
                       const float* s3, __half* d0, __half* d1, __half* d2,
                       __half* d3, int n4)
{
    int i = blockIdx.x * blockDim.x + threadIdx.x;
    if (i >= n4) return;
    const float* s; __half* d;
    switch (blockIdx.y) {
        case 0: s = s0; d = d0; break;
        case 1: s = s1; d = d1; break;
        case 2: s = s2; d = d2; break;
        default: s = s3; d = d3; break;
    }
    float4 v = ((const float4*)s)[i];
    ((uint2*)d)[i] = make_uint2(h2pack(v.x, v.y), h2pack(v.z, v.w));
}

__global__ void rope_fill(const int* __restrict__ pos)
{
    int idx = blockIdx.x * blockDim.x + threadIdx.x;
    if (idx >= SEQ * 32) return;
    int s = idx >> 5, p = idx & 31;
    float ff  = (float)(1.0 / pow(10000.0, (double)(2 * p) / 64.0));
    float ang = (float)pos[s] * ff;
    double a  = (double)ang;
    g_rope[idx * 2 + 0] = (float)cos(a);
    g_rope[idx * 2 + 1] = (float)sin(a);
}

/* ------------------------------------------------------------------ */
/* fp16 GEMM (measured-best config): 128x128 tile, warp 64x32, BK=64,  */
/* 2-stage cp.async.                                                   */
/* ------------------------------------------------------------------ */
#define GBK   64
#define KSH   72
#define ABUFH (128 * KSH)
#define STGH  (2 * ABUFH)
#define NCH   (DM / GBK)
#define GSMEM (2 * STGH * 2)

__device__ __forceinline__ void gemm_body(const __half* __restrict__ A,
                                          const __half* __restrict__ Bw,
                                          void* __restrict__ Cp, int mode,
                                          __half* hsm, int m0, int n0)
{
    uint32_t sbase = smem_u32(hsm);
    int t = threadIdx.x, lane = t & 31, w = t >> 5;
    int g = lane >> 2, tq = lane & 3;
    int wm = (w & 1) * 64, wn = (w >> 1) * 32;

    float acc[4][4][4];
#pragma unroll
    for (int mf = 0; mf < 4; mf++)
#pragma unroll
        for (int nf = 0; nf < 4; nf++)
#pragma unroll
            for (int i = 0; i < 4; i++) acc[mf][nf][i] = 0.0f;

    int arow = (lane & 7) + ((lane >> 3) & 1) * 8;
    int akoff = (lane >> 4) * 8;
    int brow = (lane & 7) + ((lane >> 4) & 1) * 8;
    int bkoff = ((lane >> 3) & 1) * 8;
    uint32_t a_off[4], b_off[2];
#pragma unroll
    for (int mf = 0; mf < 4; mf++)
        a_off[mf] = ((wm + mf * 16 + arow) * KSH + akoff) * 2;
#pragma unroll
    for (int p = 0; p < 2; p++)
        b_off[p] = ((wn + p * 16 + brow) * KSH + bkoff) * 2 + ABUFH * 2;

#define G_LOAD(cn, st) do {                                                   \
        uint32_t sa = sbase + (uint32_t)(st) * (STGH * 2);                    \
        uint32_t sbb = sa + ABUFH * 2;                                        \
        _Pragma("unroll")                                                     \
        for (int i = 0; i < 4; i++) {                                         \
            int idx = i * 256 + t, row = idx >> 3, c8 = idx & 7;              \
            cpa16(sa  + row * (KSH * 2) + c8 * 16,                            \
                  A  + (size_t)(m0 + row) * DM + (cn) * GBK + c8 * 8);        \
            cpa16(sbb + row * (KSH * 2) + c8 * 16,                            \
                  Bw + (size_t)(n0 + row) * DM + (cn) * GBK + c8 * 8);        \
        }                                                                     \
        CP_COMMIT();                                                          \
    } while (0)

    G_LOAD(0, 0);
    G_LOAD(1, 1);

#pragma unroll 1
    for (int c = 0; c < NCH; c++) {
        if (c < NCH - 1) CP_WAIT1(); else CP_WAIT0();
        __syncthreads();

        uint32_t stb = sbase + (uint32_t)(c & 1) * (STGH * 2);
#pragma unroll
        for (int ks = 0; ks < 4; ks++) {
            uint32_t kb = ks * 32;
            uint32_t af[4][4], bf[2][4];
#pragma unroll
            for (int mf = 0; mf < 4; mf++) ldm4(af[mf], stb + a_off[mf] + kb);
#pragma unroll
            for (int p = 0; p < 2; p++)    ldm4(bf[p], stb + b_off[p] + kb);
#pragma unroll
            for (int mf = 0; mf < 4; mf++)
#pragma unroll
                for (int nf = 0; nf < 4; nf++)
                    mma16(acc[mf][nf], af[mf][0], af[mf][1], af[mf][2], af[mf][3],
                          bf[nf >> 1][(nf & 1) * 2], bf[nf >> 1][(nf & 1) * 2 + 1]);
        }
        __syncthreads();
        if (c + 2 < NCH) G_LOAD(c + 2, c & 1);
    }
#undef G_LOAD

    if (mode == 3) {
        float* stg = (float*)hsm + w * (32 * 33);
        int bb = m0 >> 11;
        int gn = n0 + wn + lane;
        int hh = gn >> 6, dd = gn & 63;
#pragma unroll
        for (int hf = 0; hf < 2; hf++) {
#pragma unroll
            for (int mfl = 0; mfl < 2; mfl++) {
                int mf = hf * 2 + mfl;
                int rl = mfl * 16 + g;
#pragma unroll
                for (int nf = 0; nf < 4; nf++) {
                    int cl = nf * 8 + 2 * tq;
                    stg[rl * 33 + cl]           = acc[mf][nf][0];
                    stg[rl * 33 + cl + 1]       = acc[mf][nf][1];
                    stg[(rl + 8) * 33 + cl]     = acc[mf][nf][2];
                    stg[(rl + 8) * 33 + cl + 1] = acc[mf][nf][3];
                }
            }
            __syncwarp();
            int s0 = (m0 + wm + hf * 32) & (SEQ - 1);
            uint32_t u[16];
#pragma unroll
            for (int i = 0; i < 16; i++)
                u[i] = h2pack(stg[(2 * i) * 33 + lane], stg[(2 * i + 1) * 33 + lane]);
            uint4* dv = (uint4*)((__half*)Cp +
                        ((size_t)(bb * NH + hh) * HD + dd) * SEQ + s0);
            dv[0] = make_uint4(u[0],  u[1],  u[2],  u[3]);
            dv[1] = make_uint4(u[4],  u[5],  u[6],  u[7]);
            dv[2] = make_uint4(u[8],  u[9],  u[10], u[11]);
            dv[3] = make_uint4(u[12], u[13], u[14], u[15]);
            __syncwarp();
        }
        return;
    }

    float qscale = (mode == 1) ? 0.125f * 1.4426950408889634f : 1.0f;
#pragma unroll
    for (int mf = 0; mf < 4; mf++)
#pragma unroll
        for (int i2 = 0; i2 < 2; i2++) {
            int gm = m0 + wm + mf * 16 + g + i2 * 8;
#pragma unroll
            for (int nf = 0; nf < 4; nf++) {
                int gn = n0 + wn + nf * 8 + 2 * tq;
                float v0 = acc[mf][nf][i2 * 2 + 0];
                float v1 = acc[mf][nf][i2 * 2 + 1];
                if (mode == 0) {
                    *(float2*)((float*)Cp + (size_t)gm * DM + gn) = make_float2(v0, v1);
                } else {
                    int bb = gm >> 11, ss = gm & (SEQ - 1);
                    int hh = gn >> 6,  dd = gn & 63;
                    int p = dd >> 1;
                    float cv = g_rope[(ss * 32 + p) * 2 + 0];
                    float sv = g_rope[(ss * 32 + p) * 2 + 1];
                    uint32_t h = h2pack((v0 * cv - v1 * sv) * qscale,
                                        (v0 * sv + v1 * cv) * qscale);
                    *(uint32_t*)((__half*)Cp +
                        (((size_t)(bb * NH + hh) * SEQ) + ss) * HD + dd) = h;
                }
            }
        }
}

__global__ __launch_bounds__(256, 2) void gemm_qkv(const __half* __restrict__ xh,
    const __half* __restrict__ wq, const __half* __restrict__ wk,
    const __half* __restrict__ wv, __half* __restrict__ qh,
    __half* __restrict__ kh, __half* __restrict__ vth)
{
    extern __shared__ __half hsm[];
    const __half* Bw; void* Cp; int mode;
    if (blockIdx.z == 0)      { Bw = wq; Cp = qh;  mode = 1; }
    else if (blockIdx.z == 1) { Bw = wk; Cp = kh;  mode = 2; }
    else                      { Bw = wv; Cp = vth; mode = 3; }
    gemm_body(xh, Bw, Cp, mode, hsm, blockIdx.y * 128, blockIdx.x * 128);
}

__global__ __launch_bounds__(256, 2) void gemm_out(const __half* __restrict__ A,
    const __half* __restrict__ Bw, float* __restrict__ C)
{
    extern __shared__ __half hsm[];
    gemm_body(A, Bw, C, 0, hsm, blockIdx.y * 128, blockIdx.x * 128);
}

/* ------------------------------------------------------------------ */
/* fp16 flash, base-2 softmax. Persistent CTAs + atomic work queue     */
/* (heavy tasks first). ps/l reduction deferred past the PV mmas.      */
/* ------------------------------------------------------------------ */
#define FQS 72
#define FVS 136
#define FOFF_K (128 * FQS)
#define FOFF_V (FOFF_K + 2 * 128 * FQS)
#define FSMEM  ((FOFF_V + 2 * 64 * FVS) * 2)   /* 90112 B */
#define FLASH_GRID 304

__global__ __launch_bounds__(256, 2) void flash_h(const __half* __restrict__ gq,
                                                  const __half* __restrict__ gk,
                                                  const __half* __restrict__ gv,
                                                  __half* __restrict__ gout)
{
    extern __shared__ __half fsm[];
    __shared__ int s_task;
    uint32_t sbase = smem_u32(fsm);

    int t = threadIdx.x, lane = t & 31, w = t >> 5;
    int g = lane >> 2, tq = lane & 3;
    int qr = w * 16 + g;
    const unsigned FULL = 0xffffffffu;

    /* ldmatrix per-lane offsets (task-independent) */
    int arow = (lane & 7) + ((lane >> 3) & 1) * 8;
    int akoff = (lane >> 4) * 8;
    int brow = (lane & 7) + ((lane >> 4) & 1) * 8;
    int bkoff = ((lane >> 3) & 1) * 8;
    uint32_t q_off = ((w * 16 + arow) * FQS + akoff) * 2;
    uint32_t k_off[4], v_off[4];
#pragma unroll
    for (int p = 0; p < 4; p++) {
        k_off[p] = ((p * 16 + brow) * FQS + bkoff) * 2;
        v_off[p] = ((p * 16 + brow) * FVS + bkoff) * 2;
    }

#define F_LOADKV(ktp, nb) do {                                                \
        const __half* Kn = Kg + (size_t)(ktp) * 128 * HD;                     \
        _Pragma("unroll")                                                     \
        for (int i = 0; i < 4; i++) {                                         \
            int idx = i * 256 + t, row = idx >> 3, c8 = idx & 7;              \
            cpa16(sbase + (FOFF_K + ((nb) * 128 + row) * FQS) * 2 + c8 * 16,  \
                  Kn + row * HD + c8 * 8);                                    \
        }                                                                     \
        _Pragma("unroll")                                                     \
        for (int i = 0; i < 4; i++) {                                         \
            int idx = i * 256 + t, row = idx >> 4, c16 = idx & 15;            \
            cpa16(sbase + (FOFF_V + ((nb) * 64 + row) * FVS) * 2 + c16 * 16,  \
                  Vg + (size_t)row * SEQ + (ktp) * 128 + c16 * 8);            \
        }                                                                     \
        CP_COMMIT();                                                          \
    } while (0)

    for (;;) {
        if (t == 0) s_task = atomicAdd(&g_task, 1);
        __syncthreads();
        int task = s_task;
        if (task >= NTASK) return;
        int qt = 15 - (task >> 5);   /* heavy (long) q-tiles first */
        int bh = task & 31;

        const __half* Qg = gq + ((size_t)bh * SEQ + qt * 128) * HD;
        const __half* Kg = gk + (size_t)bh * SEQ * HD;
        const __half* Vg = gv + (size_t)bh * HD * SEQ;

#pragma unroll
        for (int i = 0; i < 4; i++) {
            int idx = i * 256 + t, row = idx >> 3, c8 = idx & 7;
            cpa16(sbase + row * (FQS * 2) + c8 * 16, Qg + row * HD + c8 * 8);
        }
        F_LOADKV(0, 0);

        float o[8][4];
#pragma unroll
        for (int nf = 0; nf < 8; nf++)
#pragma unroll
            for (int i = 0; i < 4; i++) o[nf][i] = 0.0f;
        float m0r = -1e30f, m1r = -1e30f, l0 = 0.0f, l1 = 0.0f;

        int nktp = qt + 1;
#pragma unroll 1
        for (int ktp = 0; ktp < nktp; ktp++) {
            CP_WAIT0();
            __syncthreads();
            if (ktp + 1 < nktp) F_LOADKV(ktp + 1, (ktp + 1) & 1);

            uint32_t qa[4][4];
#pragma unroll
            for (int ks = 0; ks < 4; ks++) ldm4(qa[ks], sbase + q_off + ks * 32);

            uint32_t kbb = sbase + (FOFF_K + (ktp & 1) * 128 * FQS) * 2;
            uint32_t vbb = sbase + (FOFF_V + (ktp & 1) * 64 * FVS) * 2;

#pragma unroll
            for (int hlf = 0; hlf < 2; hlf++) {
                int kt64 = ktp * 2 + hlf;
                if (kt64 * 64 > qt * 128 + w * 16 + 15) continue;

                uint32_t kbase = kbb + hlf * (64 * FQS * 2);
                uint32_t vkoff = hlf * 128;

                float s[8][4];
#pragma unroll
                for (int nf = 0; nf < 8; nf++)
                    s[nf][0] = s[nf][1] = s[nf][2] = s[nf][3] = 0.0f;
#pragma unroll
                for (int ks = 0; ks < 4; ks++) {
                    uint32_t kr[4][4];
#pragma unroll
                    for (int p = 0; p < 4; p++)
                        ldm4(kr[p], kbase + k_off[p] + ks * 32);
#pragma unroll
                    for (int nf = 0; nf < 8; nf++)
                        mma16(s[nf], qa[ks][0], qa[ks][1], qa[ks][2], qa[ks][3],
                              kr[nf >> 1][(nf & 1) * 2], kr[nf >> 1][(nf & 1) * 2 + 1]);
                }

                int gi0 = qt * 128 + w * 16 + g;
                if (kt64 * 64 + 63 > gi0) {
#pragma unroll
                    for (int nf = 0; nf < 8; nf++)
#pragma unroll
                        for (int j = 0; j < 4; j++) {
                            int col = kt64 * 64 + nf * 8 + 2 * tq + (j & 1);
                            int row = gi0 + (j >> 1) * 8;
                            if (col > row) s[nf][j] = -1e30f;
                        }
                }

                /* max reduce (critical path) */
                float mt0 = -1e30f, mt1 = -1e30f;
#pragma unroll
                for (int nf = 0; nf < 8; nf++) {
                    mt0 = fmaxf(mt0, fmaxf(s[nf][0], s[nf][1]));
                    mt1 = fmaxf(mt1, fmaxf(s[nf][2], s[nf][3]));
                }
                mt0 = fmaxf(mt0, __shfl_xor_sync(FULL, mt0, 1));
                mt0 = fmaxf(mt0, __shfl_xor_sync(FULL, mt0, 2));
                mt1 = fmaxf(mt1, __shfl_xor_sync(FULL, mt1, 1));
                mt1 = fmaxf(mt1, __shfl_xor_sync(FULL, mt1, 2));
                float mn0 = fmaxf(m0r, mt0), mn1 = fmaxf(m1r, mt1);
                float al0 = exp2f(m0r - mn0), al1 = exp2f(m1r - mn1);

                /* exp2 + local sums */
                float ps0 = 0.0f, ps1 = 0.0f;
#pragma unroll
                for (int nf = 0; nf < 8; nf++) {
                    s[nf][0] = exp2f(s[nf][0] - mn0);
                    s[nf][1] = exp2f(s[nf][1] - mn0);
                    s[nf][2] = exp2f(s[nf][2] - mn1);
                    s[nf][3] = exp2f(s[nf][3] - mn1);
                    ps0 += s[nf][0] + s[nf][1];
                    ps1 += s[nf][2] + s[nf][3];
                }
#pragma unroll
                for (int nf = 0; nf < 8; nf++) {
                    o[nf][0] *= al0; o[nf][1] *= al0;
                    o[nf][2] *= al1; o[nf][3] *= al1;
                }

                /* PV mmas issued before the ps shuffle reduction */
#pragma unroll
                for (int ks = 0; ks < 4; ks++) {
                    uint32_t pa0 = h2pack(s[2 * ks][0],     s[2 * ks][1]);
                    uint32_t pa1 = h2pack(s[2 * ks][2],     s[2 * ks][3]);
                    uint32_t pa2 = h2pack(s[2 * ks + 1][0], s[2 * ks + 1][1]);
                    uint32_t pa3 = h2pack(s[2 * ks + 1][2], s[2 * ks + 1][3]);
                    uint32_t vr[4][4];
#pragma unroll
                    for (int p = 0; p < 4; p++)
                        ldm4(vr[p], vbb + v_off[p] + vkoff + ks * 32);
#pragma unroll
                    for (int nf = 0; nf < 8; nf++)
                        mma16(o[nf], pa0, pa1, pa2, pa3,
                              vr[nf >> 1][(nf & 1) * 2], vr[nf >> 1][(nf & 1) * 2 + 1]);
                }

                /* deferred l/m update */
                ps0 += __shfl_xor_sync(FULL, ps0, 1);
                ps0 += __shfl_xor_sync(FULL, ps0, 2);
                ps1 += __shfl_xor_sync(FULL, ps1, 1);
                ps1 += __shfl_xor_sync(FULL, ps1, 2);
                l0 = l0 * al0 + ps0;  l1 = l1 * al1 + ps1;
                m0r = mn0;  m1r = mn1;
            }
        }

        int b = bh >> 4, h = bh & 15;
        float inv0 = 1.0f / l0, inv1 = 1.0f / l1;
        int s0 = qt * 128 + qr;
#pragma unroll
        for (int nf = 0; nf < 8; nf++) {
            int d = nf * 8 + 2 * tq;
            *(uint32_t*)(gout + ((size_t)b * SEQ + s0) * DM + h * 64 + d) =
                h2pack(o[nf][0] * inv0, o[nf][1] * inv0);
            *(uint32_t*)(gout + ((size_t)b * SEQ + s0 + 8) * DM + h * 64 + d) =
                h2pack(o[nf][2] * inv1, o[nf][3] * inv1);
        }
        __syncthreads();   /* protect smem before next task */
    }
#undef F_LOADKV
}

/* ------------------------------------------------------------------ */
extern "C" void kernel_launch(void* const* d_in, const int* in_sizes, int n_in,
                              void* d_out, int out_size)
{
    const float* x  = (const float*)d_in[0];
    const float* Wq = (const float*)d_in[1];
    const float* Wk = (const float*)d_in[2];
    const float* Wv = (const float*)d_in[3];
    const float* Wo = (const float*)d_in[4];
    const int*  pos = (const int*)d_in[6];
    float* out = (float*)d_out;

    __half *xh, *wqh, *wkh, *wvh, *woh, *qh, *kh, *vth, *ath;
    int* taskp;
    cudaGetSymbolAddress((void**)&xh,  g_xh);
    cudaGetSymbolAddress((void**)&wqh, g_wqh);
    cudaGetSymbolAddress((void**)&wkh, g_wkh);
    cudaGetSymbolAddress((void**)&wvh, g_wvh);
    cudaGetSymbolAddress((void**)&woh, g_woh);
    cudaGetSymbolAddress((void**)&qh,  g_qh);
    cudaGetSymbolAddress((void**)&kh,  g_kh);
    cudaGetSymbolAddress((void**)&vth, g_vth);
    cudaGetSymbolAddress((void**)&ath, g_ath);
    cudaGetSymbolAddress((void**)&taskp, g_task);

    cudaFuncSetAttribute(gemm_qkv, cudaFuncAttributeMaxDynamicSharedMemorySize, GSMEM);
    cudaFuncSetAttribute(gemm_out, cudaFuncAttributeMaxDynamicSharedMemorySize, GSMEM);
    cudaFuncSetAttribute(flash_h,  cudaFuncAttributeMaxDynamicSharedMemorySize, FSMEM);

    int nx4 = MROWS * DM / 4, nw4 = DM * DM / 4;
    f2h_k<<<(nx4 + 255) / 256, 256>>>(x, xh, nx4);
    f2h4_k<<<dim3((nw4 + 255) / 256, 4), 256>>>(Wq, Wk, Wv, Wo,
                                                wqh, wkh, wvh, woh, nw4);
    rope_fill<<<256, 256>>>(pos);
    cudaMemsetAsync(taskp, 0, sizeof(int));

    gemm_qkv<<<dim3(DM / 128, MROWS / 128, 3), 256, GSMEM>>>(
        xh, wqh, wkh, wvh, qh, kh, vth);

    flash_h<<<FLASH_GRID, 256, FSMEM>>>(qh, kh, vth, ath);

    gemm_out<<<dim3(DM / 128, MROWS / 128), 256, GSMEM>>>(ath, woh, out);
}